// round 1
// baseline (speedup 1.0000x reference)
#include <cuda_runtime.h>
#include <math.h>
#include <stdint.h>

#define Bsz 2
#define Lseq 2048
#define Dm 1024
#define Hh 16
#define HDd 64
#define BL (Bsz*Lseq)   // 4096

// ---------------- scratch (static device globals; no allocation) ----------------
__device__ float g_qkv[BL*3*Dm];   // x @ Wqkv  (B,L,3,H,HD)
__device__ float g_attn[BL*Dm];    // attention output (B,L,D)
__device__ float g_flash[BL*Dm];   // attn @ Wout, then LN in place
__device__ float g_dqr[BL*Dm];     // x @ dWq (pre-conv)
__device__ float g_dkr[BL*Dm];     // x @ dWk (pre-conv)
__device__ float g_dq[BL*Dm];      // conv'd q
__device__ float g_dk[BL*Dm];      // conv'd + normalized k
__device__ float g_dv[BL*Dm];      // x @ dWv
__device__ float g_beta[BL*Hh];    // x @ Wbeta (pre-sigmoid, pre-bias)
__device__ float g_ys[BL*Dm];      // scan outputs
__device__ float g_delta[BL*Dm];   // ys @ dWo, LN twice in place
__device__ float g_gate[BL*Dm];    // x @ Wgate (pre-sigmoid)

// ---------------- SGEMM: C[M,N] = A[M,K] @ B[K,N], row-major ----------------
// BM=128, BN=64, BK=16, 256 threads, 8x4 microtile.
__global__ void gemm128(const float* __restrict__ A, const float* __restrict__ Bm,
                        float* __restrict__ C, int M, int N, int K) {
    __shared__ float As[16][128];
    __shared__ float Bs[16][64];
    int tid = threadIdx.x;
    int tx = tid & 15, ty = tid >> 4;          // ty: 0..15
    int m0 = blockIdx.y * 128, n0 = blockIdx.x * 64;

    int arow = tid >> 2;                        // 0..63
    int ak4  = (tid & 3) * 4;                   // k offset within 16
    int brow = tid >> 4;                        // 0..15
    int bc4  = (tid & 15) * 4;                  // n offset within 64

    float acc[8][4];
#pragma unroll
    for (int i = 0; i < 8; i++)
#pragma unroll
        for (int j = 0; j < 4; j++) acc[i][j] = 0.f;

    for (int kk = 0; kk < K; kk += 16) {
#pragma unroll
        for (int half = 0; half < 2; half++) {
            int r = arow + half * 64;
            float4 a4 = *(const float4*)&A[(size_t)(m0 + r) * K + kk + ak4];
            As[ak4 + 0][r] = a4.x; As[ak4 + 1][r] = a4.y;
            As[ak4 + 2][r] = a4.z; As[ak4 + 3][r] = a4.w;
        }
        if (n0 + bc4 < N) {
            *(float4*)&Bs[brow][bc4] = *(const float4*)&Bm[(size_t)(kk + brow) * N + n0 + bc4];
        } else {
            *(float4*)&Bs[brow][bc4] = make_float4(0.f, 0.f, 0.f, 0.f);
        }
        __syncthreads();
#pragma unroll
        for (int k2 = 0; k2 < 16; k2++) {
            float4 b4 = *(float4*)&Bs[k2][tx * 4];
            float4 aa = *(float4*)&As[k2][ty * 8];
            float4 ab = *(float4*)&As[k2][ty * 8 + 4];
            float av[8] = {aa.x, aa.y, aa.z, aa.w, ab.x, ab.y, ab.z, ab.w};
            float bv[4] = {b4.x, b4.y, b4.z, b4.w};
#pragma unroll
            for (int i = 0; i < 8; i++)
#pragma unroll
                for (int j = 0; j < 4; j++) acc[i][j] += av[i] * bv[j];
        }
        __syncthreads();
    }
    if (n0 + tx * 4 < N) {
#pragma unroll
        for (int i = 0; i < 8; i++) {
            int row = m0 + ty * 8 + i;
            float4 o = make_float4(acc[i][0], acc[i][1], acc[i][2], acc[i][3]);
            *(float4*)&C[(size_t)row * N + n0 + tx * 4] = o;
        }
    }
}

// ---------------- conv (causal depthwise, KW=4) + k-normalization ----------------
__global__ void conv_kernel(const float* __restrict__ dqr, const float* __restrict__ dkr,
                            const float* __restrict__ cqw, const float* __restrict__ cqb,
                            const float* __restrict__ ckw, const float* __restrict__ ckb,
                            float* __restrict__ dq, float* __restrict__ dk) {
    int bt = blockIdx.x;            // 0..4095  (b*L + t)
    int t  = bt & (Lseq - 1);
    int tid = threadIdx.x;          // 256
    int c0 = tid * 4;

    float xq[4][4], xk[4][4];
#pragma unroll
    for (int j = 0; j < 4; j++) {
        int tt = t - 3 + j;
        if (tt >= 0) {
            float4 a = *(const float4*)&dqr[(size_t)(bt - 3 + j) * Dm + c0];
            xq[j][0] = a.x; xq[j][1] = a.y; xq[j][2] = a.z; xq[j][3] = a.w;
            float4 b = *(const float4*)&dkr[(size_t)(bt - 3 + j) * Dm + c0];
            xk[j][0] = b.x; xk[j][1] = b.y; xk[j][2] = b.z; xk[j][3] = b.w;
        } else {
#pragma unroll
            for (int u = 0; u < 4; u++) { xq[j][u] = 0.f; xk[j][u] = 0.f; }
        }
    }
    float4 qb4 = *(const float4*)&cqb[c0];
    float4 kb4 = *(const float4*)&ckb[c0];
    float qbv[4] = {qb4.x, qb4.y, qb4.z, qb4.w};
    float kbv[4] = {kb4.x, kb4.y, kb4.z, kb4.w};

    float oq[4], ok[4];
#pragma unroll
    for (int u = 0; u < 4; u++) {
        float4 wq = *(const float4*)&cqw[(c0 + u) * 4];
        float4 wk = *(const float4*)&ckw[(c0 + u) * 4];
        oq[u] = qbv[u] + wq.x * xq[0][u] + wq.y * xq[1][u] + wq.z * xq[2][u] + wq.w * xq[3][u];
        ok[u] = kbv[u] + wk.x * xk[0][u] + wk.y * xk[1][u] + wk.z * xk[2][u] + wk.w * xk[3][u];
    }
    *(float4*)&dq[(size_t)bt * Dm + c0] = make_float4(oq[0], oq[1], oq[2], oq[3]);

    // per-head L2 norm over 64 channels = 16 threads (contiguous 16-lane group)
    float ss = ok[0] * ok[0] + ok[1] * ok[1] + ok[2] * ok[2] + ok[3] * ok[3];
    ss += __shfl_xor_sync(0xffffffffu, ss, 1, 16);
    ss += __shfl_xor_sync(0xffffffffu, ss, 2, 16);
    ss += __shfl_xor_sync(0xffffffffu, ss, 4, 16);
    ss += __shfl_xor_sync(0xffffffffu, ss, 8, 16);
    float rn = 1.f / fmaxf(sqrtf(ss), 1e-12f);
    *(float4*)&dk[(size_t)bt * Dm + c0] =
        make_float4(ok[0] * rn, ok[1] * rn, ok[2] * rn, ok[3] * rn);
}

// ---------------- causal flash attention (fp32, streaming) ----------------
// grid: (qtile=32, b*H=32), 256 threads, 64KB dynamic smem.
__global__ void attn_kernel(const float* __restrict__ qkv, float* __restrict__ out) {
    extern __shared__ float sm[];
    float (*Qs)[64] = (float(*)[64])(sm);            // [d][r]
    float (*Ks)[64] = (float(*)[64])(sm + 4096);     // [d][c]
    float (*Vs)[64] = (float(*)[64])(sm + 8192);     // [k][c]
    float (*Ps)[64] = (float(*)[64])(sm + 12288);    // [k][r]

    int qt = blockIdx.x, bh = blockIdx.y;
    int b = bh >> 4, h = bh & 15;
    int tid = threadIdx.x;
    int tx = tid & 15, ty = tid >> 4;
    int q0 = qt * 64;
    size_t qkvbase = (size_t)(b * Lseq) * 3072 + h * 64;

    int lr = tid >> 2;                // row 0..63
    int ldb = (tid & 3) * 16;         // d-chunk base

#pragma unroll
    for (int i = 0; i < 16; i += 4) {
        float4 a = *(const float4*)&qkv[qkvbase + (size_t)(q0 + lr) * 3072 + ldb + i];
        Qs[ldb + i + 0][lr] = a.x; Qs[ldb + i + 1][lr] = a.y;
        Qs[ldb + i + 2][lr] = a.z; Qs[ldb + i + 3][lr] = a.w;
    }

    float acc[4][4];
    float m_i[4], l_i[4];
#pragma unroll
    for (int i = 0; i < 4; i++) {
        m_i[i] = -1e30f; l_i[i] = 0.f;
#pragma unroll
        for (int j = 0; j < 4; j++) acc[i][j] = 0.f;
    }
    __syncthreads();

    for (int kt = 0; kt <= qt; kt++) {
        int k0 = kt * 64;
#pragma unroll
        for (int i = 0; i < 16; i += 4) {
            float4 a = *(const float4*)&qkv[qkvbase + 1024 + (size_t)(k0 + lr) * 3072 + ldb + i];
            Ks[ldb + i + 0][lr] = a.x; Ks[ldb + i + 1][lr] = a.y;
            Ks[ldb + i + 2][lr] = a.z; Ks[ldb + i + 3][lr] = a.w;
            float4 v = *(const float4*)&qkv[qkvbase + 2048 + (size_t)(k0 + lr) * 3072 + ldb + i];
            *(float4*)&Vs[lr][ldb + i] = v;
        }
        __syncthreads();

        float s[4][4];
#pragma unroll
        for (int i = 0; i < 4; i++)
#pragma unroll
            for (int j = 0; j < 4; j++) s[i][j] = 0.f;
#pragma unroll
        for (int d = 0; d < 64; d++) {
            float4 a = *(float4*)&Qs[d][ty * 4];
            float4 bq = *(float4*)&Ks[d][tx * 4];
            float av[4] = {a.x, a.y, a.z, a.w};
            float bv[4] = {bq.x, bq.y, bq.z, bq.w};
#pragma unroll
            for (int i = 0; i < 4; i++)
#pragma unroll
                for (int j = 0; j < 4; j++) s[i][j] += av[i] * bv[j];
        }
        if (kt == qt) {
#pragma unroll
            for (int i = 0; i < 4; i++)
#pragma unroll
                for (int j = 0; j < 4; j++) {
                    if (tx * 4 + j > ty * 4 + i) s[i][j] = -1e30f;
                    else s[i][j] *= 0.125f;
                }
        } else {
#pragma unroll
            for (int i = 0; i < 4; i++)
#pragma unroll
                for (int j = 0; j < 4; j++) s[i][j] *= 0.125f;
        }
        // online softmax per row (row group = 16 lanes sharing ty)
#pragma unroll
        for (int i = 0; i < 4; i++) {
            float mm = fmaxf(fmaxf(s[i][0], s[i][1]), fmaxf(s[i][2], s[i][3]));
            mm = fmaxf(mm, __shfl_xor_sync(0xffffffffu, mm, 1, 16));
            mm = fmaxf(mm, __shfl_xor_sync(0xffffffffu, mm, 2, 16));
            mm = fmaxf(mm, __shfl_xor_sync(0xffffffffu, mm, 4, 16));
            mm = fmaxf(mm, __shfl_xor_sync(0xffffffffu, mm, 8, 16));
            float mt = fmaxf(m_i[i], mm);
            float alpha = __expf(m_i[i] - mt);
            m_i[i] = mt;
            float rs = 0.f;
#pragma unroll
            for (int j = 0; j < 4; j++) { s[i][j] = __expf(s[i][j] - mt); rs += s[i][j]; }
            rs += __shfl_xor_sync(0xffffffffu, rs, 1, 16);
            rs += __shfl_xor_sync(0xffffffffu, rs, 2, 16);
            rs += __shfl_xor_sync(0xffffffffu, rs, 4, 16);
            rs += __shfl_xor_sync(0xffffffffu, rs, 8, 16);
            l_i[i] = l_i[i] * alpha + rs;
#pragma unroll
            for (int j = 0; j < 4; j++) acc[i][j] *= alpha;
        }
#pragma unroll
        for (int j = 0; j < 4; j++) {
            float4 pv = make_float4(s[0][j], s[1][j], s[2][j], s[3][j]);
            *(float4*)&Ps[tx * 4 + j][ty * 4] = pv;
        }
        __syncthreads();
#pragma unroll
        for (int kk = 0; kk < 64; kk++) {
            float4 a = *(float4*)&Ps[kk][ty * 4];
            float4 bv4 = *(float4*)&Vs[kk][tx * 4];
            float av[4] = {a.x, a.y, a.z, a.w};
            float bv[4] = {bv4.x, bv4.y, bv4.z, bv4.w};
#pragma unroll
            for (int i = 0; i < 4; i++)
#pragma unroll
                for (int j = 0; j < 4; j++) acc[i][j] += av[i] * bv[j];
        }
        __syncthreads();
    }
    size_t obase = (size_t)(b * Lseq) * Dm + h * 64;
#pragma unroll
    for (int i = 0; i < 4; i++) {
        float inv = 1.f / l_i[i];
        float4 o = make_float4(acc[i][0] * inv, acc[i][1] * inv, acc[i][2] * inv, acc[i][3] * inv);
        *(float4*)&out[obase + (size_t)(q0 + ty * 4 + i) * Dm + tx * 4] = o;
    }
}

// ---------------- sequential delta scan: 32 CTAs (b,h), 256 threads ----------------
__global__ void scan_kernel(const float* __restrict__ dq, const float* __restrict__ dk,
                            const float* __restrict__ dv, const float* __restrict__ beta_pre,
                            const float* __restrict__ bbeta,
                            float* __restrict__ ys, float* __restrict__ outS,
                            float* __restrict__ outZ) {
    int bh = blockIdx.x;
    int b = bh >> 4, h = bh & 15;
    int tid = threadIdx.x;
    int r = tid >> 2, qq = tid & 3, c0 = qq * 16;
    int lane = tid & 63, g = tid >> 6;

    __shared__ float qs[64], ks[64], vs[64], zs[64];
    __shared__ float red[8];
    __shared__ float sbeta;

    float S[16];
#pragma unroll
    for (int j = 0; j < 16; j++) S[j] = 0.f;
    if (tid < 64) zs[tid] = 0.f;

    size_t rowbase = (size_t)(b * Lseq) * Dm + (size_t)h * 64;
    size_t betabase = (size_t)(b * Lseq) * Hh + h;

    float pre = 0.f;
    if (g == 0) pre = dq[rowbase + lane];
    else if (g == 1) pre = dk[rowbase + lane];
    else if (g == 2) pre = dv[rowbase + lane];
    else if (lane == 0) pre = beta_pre[betabase] + bbeta[h];

    for (int t = 0; t < Lseq; t++) {
        if (g == 0) qs[lane] = pre;
        else if (g == 1) ks[lane] = pre;
        else if (g == 2) vs[lane] = pre;
        else if (lane == 0) sbeta = 1.f / (1.f + __expf(-pre));
        __syncthreads();   // A: staged data + prior z visible

        if (t + 1 < Lseq) {   // prefetch next step (latency overlapped with compute)
            size_t row = rowbase + (size_t)(t + 1) * Dm;
            if (g == 0) pre = dq[row + lane];
            else if (g == 1) pre = dk[row + lane];
            else if (g == 2) pre = dv[row + lane];
            else if (lane == 0) pre = beta_pre[betabase + (size_t)(t + 1) * Hh] + bbeta[h];
        }

        float accy = 0.f, acco = 0.f;
#pragma unroll
        for (int j = 0; j < 16; j += 4) {
            float4 q4 = *(float4*)&qs[c0 + j];
            float4 k4 = *(float4*)&ks[c0 + j];
            accy += S[j] * q4.x + S[j + 1] * q4.y + S[j + 2] * q4.z + S[j + 3] * q4.w;
            acco += S[j] * k4.x + S[j + 1] * k4.y + S[j + 2] * k4.z + S[j + 3] * k4.w;
        }
        accy += __shfl_xor_sync(0xffffffffu, accy, 1);
        accy += __shfl_xor_sync(0xffffffffu, accy, 2);
        acco += __shfl_xor_sync(0xffffffffu, acco, 1);
        acco += __shfl_xor_sync(0xffffffffu, acco, 2);

        float dp = (tid < 64) ? zs[tid] * qs[tid] : 0.f;
#pragma unroll
        for (int off = 16; off >= 1; off >>= 1) dp += __shfl_xor_sync(0xffffffffu, dp, off);
        if ((tid & 31) == 0) red[tid >> 5] = dp;
        __syncthreads();   // B: red visible; all zs reads done

        float denom = red[0] + red[1] + 1e-6f;
        float bet = sbeta;
        float delta = vs[r] - acco;
        if (qq == 0) ys[rowbase + (size_t)t * Dm + r] = accy / denom;

        float bd = bet * delta;
#pragma unroll
        for (int j = 0; j < 16; j += 4) {
            float4 k4 = *(float4*)&ks[c0 + j];
            S[j] += bd * k4.x; S[j + 1] += bd * k4.y;
            S[j + 2] += bd * k4.z; S[j + 3] += bd * k4.w;
        }
        if (tid < 64) zs[tid] += bet * ks[tid];
        __syncthreads();   // C: ks/zs reads done before next staging
    }

    size_t sb = (size_t)bh * 4096;
#pragma unroll
    for (int j = 0; j < 16; j++) outS[sb + (size_t)r * 64 + c0 + j] = S[j];
    if (tid < 64) outZ[(size_t)bh * 64 + tid] = zs[tid];
}

// ---------------- layernorm (in-place, one row per block) ----------------
__global__ void ln_kernel(float* __restrict__ x, const float* __restrict__ gw,
                          const float* __restrict__ bw) {
    __shared__ float rs[8], rq[8];
    int row = blockIdx.x, tid = threadIdx.x;
    float* xr = x + (size_t)row * Dm;
    float4 v = *(float4*)&xr[tid * 4];
    float s = v.x + v.y + v.z + v.w;
    float s2 = v.x * v.x + v.y * v.y + v.z * v.z + v.w * v.w;
#pragma unroll
    for (int off = 16; off >= 1; off >>= 1) {
        s  += __shfl_xor_sync(0xffffffffu, s, off);
        s2 += __shfl_xor_sync(0xffffffffu, s2, off);
    }
    if ((tid & 31) == 0) { rs[tid >> 5] = s; rq[tid >> 5] = s2; }
    __syncthreads();
    float tot = 0.f, tot2 = 0.f;
#pragma unroll
    for (int w = 0; w < 8; w++) { tot += rs[w]; tot2 += rq[w]; }
    float mean = tot * (1.f / 1024.f);
    float var = tot2 * (1.f / 1024.f) - mean * mean;
    float rstd = rsqrtf(var + 1e-5f);
    float4 g4 = *(const float4*)&gw[tid * 4];
    float4 b4 = *(const float4*)&bw[tid * 4];
    v.x = (v.x - mean) * rstd * g4.x + b4.x;
    v.y = (v.y - mean) * rstd * g4.y + b4.y;
    v.z = (v.z - mean) * rstd * g4.z + b4.z;
    v.w = (v.w - mean) * rstd * g4.w + b4.w;
    *(float4*)&xr[tid * 4] = v;
}

// ---------------- final gate fusion ----------------
__global__ void gate_kernel(const float* __restrict__ gp, const float* __restrict__ bg,
                            const float* __restrict__ fl, const float* __restrict__ dl,
                            float* __restrict__ out) {
    int row = blockIdx.x, tid = threadIdx.x;
    size_t i = (size_t)row * Dm + tid * 4;
    float4 gpv = *(const float4*)&gp[i];
    float4 bgv = *(const float4*)&bg[tid * 4];
    float4 flv = *(const float4*)&fl[i];
    float4 dlv = *(const float4*)&dl[i];
    float4 o;
    {
        float g0 = 1.f / (1.f + __expf(-(gpv.x + bgv.x))); o.x = g0 * flv.x + (1.f - g0) * dlv.x;
        float g1 = 1.f / (1.f + __expf(-(gpv.y + bgv.y))); o.y = g1 * flv.y + (1.f - g1) * dlv.y;
        float g2 = 1.f / (1.f + __expf(-(gpv.z + bgv.z))); o.z = g2 * flv.z + (1.f - g2) * dlv.z;
        float g3 = 1.f / (1.f + __expf(-(gpv.w + bgv.w))); o.w = g3 * flv.w + (1.f - g3) * dlv.w;
    }
    *(float4*)&out[i] = o;
}

// ---------------- launcher ----------------
extern "C" void kernel_launch(void* const* d_in, const int* in_sizes, int n_in,
                              void* d_out, int out_size) {
    const float* x     = (const float*)d_in[0];
    const float* Wqkv  = (const float*)d_in[1];
    const float* Wout  = (const float*)d_in[2];
    const float* Wgate = (const float*)d_in[3];
    const float* bgate = (const float*)d_in[4];
    const float* fn_g  = (const float*)d_in[5];
    const float* fn_b  = (const float*)d_in[6];
    const float* dn_g  = (const float*)d_in[7];
    const float* dn_b  = (const float*)d_in[8];
    const float* dWq   = (const float*)d_in[9];
    const float* dWk   = (const float*)d_in[10];
    const float* dWv   = (const float*)d_in[11];
    const float* dWo   = (const float*)d_in[12];
    const float* Wbeta = (const float*)d_in[13];
    const float* bbeta = (const float*)d_in[14];
    const float* cq_w  = (const float*)d_in[15];
    const float* cq_b  = (const float*)d_in[16];
    const float* ck_w  = (const float*)d_in[17];
    const float* ck_b  = (const float*)d_in[18];
    const float* ln_g  = (const float*)d_in[19];
    const float* ln_b  = (const float*)d_in[20];
    float* out = (float*)d_out;

    float *p_qkv, *p_attn, *p_flash, *p_dqr, *p_dkr, *p_dq, *p_dk, *p_dv;
    float *p_beta, *p_ys, *p_delta, *p_gate;
    cudaGetSymbolAddress((void**)&p_qkv,  g_qkv);
    cudaGetSymbolAddress((void**)&p_attn, g_attn);
    cudaGetSymbolAddress((void**)&p_flash,g_flash);
    cudaGetSymbolAddress((void**)&p_dqr,  g_dqr);
    cudaGetSymbolAddress((void**)&p_dkr,  g_dkr);
    cudaGetSymbolAddress((void**)&p_dq,   g_dq);
    cudaGetSymbolAddress((void**)&p_dk,   g_dk);
    cudaGetSymbolAddress((void**)&p_dv,   g_dv);
    cudaGetSymbolAddress((void**)&p_beta, g_beta);
    cudaGetSymbolAddress((void**)&p_ys,   g_ys);
    cudaGetSymbolAddress((void**)&p_delta,g_delta);
    cudaGetSymbolAddress((void**)&p_gate, g_gate);

    // S,z live at the tail of d_out (tuple output). If harness only compares
    // `out`, write them into scratch instead.
    float* pS = (out_size >= 4327424) ? out + 4194304 : p_qkv;   // qkv dead by scan time
    float* pZ = (out_size >= 4327424) ? out + 4325376 : p_qkv + 4096;

    // projections
    gemm128<<<dim3(48, 32), 256>>>(x, Wqkv,  p_qkv,  BL, 3 * Dm, Dm);
    gemm128<<<dim3(16, 32), 256>>>(x, dWq,   p_dqr,  BL, Dm, Dm);
    gemm128<<<dim3(16, 32), 256>>>(x, dWk,   p_dkr,  BL, Dm, Dm);
    gemm128<<<dim3(16, 32), 256>>>(x, dWv,   p_dv,   BL, Dm, Dm);
    gemm128<<<dim3(16, 32), 256>>>(x, Wgate, p_gate, BL, Dm, Dm);
    gemm128<<<dim3(1, 32), 256>>>(x, Wbeta, p_beta, BL, Hh, Dm);

    // conv + k-normalize
    conv_kernel<<<BL, 256>>>(p_dqr, p_dkr, cq_w, cq_b, ck_w, ck_b, p_dq, p_dk);

    // flash attention
    cudaFuncSetAttribute(attn_kernel, cudaFuncAttributeMaxDynamicSharedMemorySize, 65536);
    attn_kernel<<<dim3(32, 32), 256, 65536>>>(p_qkv, p_attn);
    gemm128<<<dim3(16, 32), 256>>>(p_attn, Wout, p_flash, BL, Dm, Dm);
    ln_kernel<<<BL, 256>>>(p_flash, fn_g, fn_b);

    // delta scan
    scan_kernel<<<32, 256>>>(p_dq, p_dk, p_dv, p_beta, bbeta, p_ys, pS, pZ);
    gemm128<<<dim3(16, 32), 256>>>(p_ys, dWo, p_delta, BL, Dm, Dm);
    ln_kernel<<<BL, 256>>>(p_delta, ln_g, ln_b);
    ln_kernel<<<BL, 256>>>(p_delta, dn_g, dn_b);

    // gate
    gate_kernel<<<BL, 256>>>(p_gate, bgate, p_flash, p_delta, out);
}